// round 2
// baseline (speedup 1.0000x reference)
#include <cuda_runtime.h>
#include <math.h>

#define BATCH  16
#define CC     64
#define MM     4096
#define NSPLIT 32
#define CHUNK  128
#define LDC    65   // cov smem row stride (scalar reads; conflict-minimal)
#define LDN    68   // ns smem row stride (float4-aligned B-row reads)

typedef unsigned long long ull;

__device__ __forceinline__ ull pack2(float lo, float hi) {
    ull r; asm("mov.b64 %0,{%1,%2};" : "=l"(r) : "f"(lo), "f"(hi)); return r;
}
__device__ __forceinline__ void unpack2(ull v, float& lo, float& hi) {
    asm("mov.b64 {%0,%1},%2;" : "=f"(lo), "=f"(hi) : "l"(v));
}
__device__ __forceinline__ ull fma2(ull a, ull b, ull c) {
    ull d; asm("fma.rn.f32x2 %0,%1,%2,%3;" : "=l"(d) : "l"(a), "l"(b), "l"(c)); return d;
}

// Deterministic scratch
__device__ float g_part[BATCH * NSPLIT * CC * CC];   // 8 MB partial Grams
__device__ float g_rspart[BATCH * NSPLIT * CC];
__device__ float g_cov[BATCH * CC * CC];
__device__ float g_scale[BATCH * CC];

// ---------------------------------------------------------------------------
// Kernel 1: partial X·X^T per (batch, M-split) + partial row sums.
// grid (NSPLIT, BATCH), 64 threads, 8x8 register tiles, f32x2 FMA.
// smem row-major buf[row][k] (LDC=65): conflict-free stores & a-reads.
// ---------------------------------------------------------------------------
__global__ __launch_bounds__(64) void cov_kernel(const float* __restrict__ x) {
    __shared__ float buf[64 * LDC];
    const int split = blockIdx.x, b = blockIdx.y;
    const int t = threadIdx.x;
    const int tx = t & 7, ty = t >> 3;
    const float* xb = x + (size_t)b * CC * MM + split * CHUNK;

    ull acc[8][4];
#pragma unroll
    for (int i = 0; i < 8; i++)
#pragma unroll
        for (int c = 0; c < 4; c++) acc[i][c] = 0ull;
    float rs = 0.f;

    const float* Ar = buf + (8 * ty) * LDC;
    const float* Br = buf + (8 * tx) * LDC;

    for (int kk = 0; kk < CHUNK / 64; kk++) {
        __syncthreads();
        // Coalesced load, conflict-free smem stores (lane t -> bank t).
#pragma unroll 8
        for (int j = 0; j < 64; j++)
            buf[j * LDC + t] = xb[(size_t)j * MM + kk * 64 + t];
        __syncthreads();
        // Row sum: lane t sums row t (conflict-free: (t*65+k)%32 distinct).
        {
            float s = 0.f;
#pragma unroll 16
            for (int k = 0; k < 64; k++) s += buf[t * LDC + k];
            rs += s;
        }
        // Rank-64 update, 8x8 tile per thread.
#pragma unroll 4
        for (int k = 0; k < 64; k++) {
            float av[8], bv[8];
#pragma unroll
            for (int i = 0; i < 8; i++) av[i] = Ar[i * LDC + k];
#pragma unroll
            for (int j = 0; j < 8; j++) bv[j] = Br[j * LDC + k];
            ull bp[4];
#pragma unroll
            for (int c = 0; c < 4; c++) bp[c] = pack2(bv[2 * c], bv[2 * c + 1]);
#pragma unroll
            for (int i = 0; i < 8; i++) {
                ull da = pack2(av[i], av[i]);
#pragma unroll
                for (int c = 0; c < 4; c++) acc[i][c] = fma2(da, bp[c], acc[i][c]);
            }
        }
    }

    float* P = g_part + (((size_t)(b * NSPLIT + split)) << 12);
#pragma unroll
    for (int i = 0; i < 8; i++)
#pragma unroll
        for (int c = 0; c < 4; c++) {
            float lo, hi; unpack2(acc[i][c], lo, hi);
            P[(8 * ty + i) * 64 + 8 * tx + 2 * c]     = lo;
            P[(8 * ty + i) * 64 + 8 * tx + 2 * c + 1] = hi;
        }
    g_rspart[(b * NSPLIT + split) * 64 + t] = rs;
}

// ---------------------------------------------------------------------------
// Kernel 2: reduce partial Grams across splits (fully parallel).
// ---------------------------------------------------------------------------
__global__ __launch_bounds__(256) void reduce_kernel() {
    int idx = blockIdx.x * 256 + threadIdx.x;       // 0 .. 16*4096-1
    int b = idx >> 12, e = idx & 4095;
    float s = 0.f;
#pragma unroll
    for (int sp = 0; sp < NSPLIT; sp++)
        s += g_part[(((size_t)(b * NSPLIT + sp)) << 12) + e];
    g_cov[idx] = s;
}

// ---------------------------------------------------------------------------
// 64x64x64 smem matmul, f32x2. 256 threads, 1 row x 16 cols per thread.
// mode 0: C = A@B ; mode 1: C = 0.5*(3I - A@B)
// Precondition: operands visible (caller sync / previous mm's exit sync).
// ---------------------------------------------------------------------------
__device__ __forceinline__ void mm64(float* __restrict__ C, const float* __restrict__ A,
                                     const float* __restrict__ B, int tx, int ty, int mode) {
    ull acc[8];
#pragma unroll
    for (int c = 0; c < 8; c++) acc[c] = 0ull;

    const float* Arow = A + ty * LDN;       // ty = row 0..63
    const float* Bc = B + 16 * tx;          // tx = col group 0..3

#pragma unroll 8
    for (int k = 0; k < 64; k++) {
        float a = Arow[k];
        ull da = pack2(a, a);
        const ulonglong2* bp = (const ulonglong2*)(Bc + k * LDN);
        ulonglong2 q0 = bp[0], q1 = bp[1], q2 = bp[2], q3 = bp[3];
        acc[0] = fma2(da, q0.x, acc[0]); acc[1] = fma2(da, q0.y, acc[1]);
        acc[2] = fma2(da, q1.x, acc[2]); acc[3] = fma2(da, q1.y, acc[3]);
        acc[4] = fma2(da, q2.x, acc[4]); acc[5] = fma2(da, q2.y, acc[5]);
        acc[6] = fma2(da, q3.x, acc[6]); acc[7] = fma2(da, q3.y, acc[7]);
    }
    __syncthreads();   // all operand reads done before C overwrites anything
#pragma unroll
    for (int c = 0; c < 8; c++) {
        float lo, hi; unpack2(acc[c], lo, hi);
        int j = 16 * tx + 2 * c;
        if (mode) {
            lo = 0.5f * (((ty == j)     ? 3.f : 0.f) - lo);
            hi = 0.5f * (((ty == j + 1) ? 3.f : 0.f) - hi);
        }
        *(float2*)&C[ty * LDN + j] = make_float2(lo, hi);
    }
    __syncthreads();   // C visible
}

// ---------------------------------------------------------------------------
// Kernel 3: covariance assembly + Newton-Schulz + center-tap convs.
// 16 blocks x 256 threads. Dynamic smem: 4 matrices [64][LDN].
// ---------------------------------------------------------------------------
__global__ __launch_bounds__(256) void ns_kernel(const float* __restrict__ w1, const float* __restrict__ b1,
                                                 const float* __restrict__ w2, const float* __restrict__ b2) {
    extern __shared__ float sm[];
    float* S0 = sm;
    float* S1 = sm + 64 * LDN;
    float* S2 = sm + 2 * 64 * LDN;
    float* S3 = sm + 3 * 64 * LDN;
    __shared__ float svec[64];
    __shared__ float vvec[64];
    __shared__ float red[8];
    __shared__ float snorm;

    const int b = blockIdx.x, t = threadIdx.x;
    const int tx = t & 3, ty = t >> 2;
    const float invM = 1.0f / (float)MM;
    const float invM2 = invM * invM;

    // row sums
    if (t < 64) {
        float s = 0.f;
        for (int sp = 0; sp < NSPLIT; sp++) s += g_rspart[(b * NSPLIT + sp) * 64 + t];
        svec[t] = s;
    }
    __syncthreads();

    // cov = Sxx/M - s s^T / M^2 ; normA = sum(cov)
    float lsum = 0.f;
#pragma unroll
    for (int e = 0; e < 16; e++) {
        int idx = e * 256 + t;
        int i = idx >> 6, j = idx & 63;
        float cv = invM * g_cov[b * 4096 + idx] - invM2 * svec[i] * svec[j];
        S0[i * LDN + j] = cv;
        lsum += cv;
    }
#pragma unroll
    for (int o = 16; o; o >>= 1) lsum += __shfl_xor_sync(0xffffffffu, lsum, o);
    if ((t & 31) == 0) red[t >> 5] = lsum;
    __syncthreads();
    if (t == 0) { float s = 0.f; for (int w = 0; w < 8; w++) s += red[w]; snorm = s; }
    __syncthreads();

    const float invN = 1.f / snorm;
#pragma unroll
    for (int e = 0; e < 16; e++) {
        int idx = e * 256 + t;
        int i = idx >> 6, j = idx & 63;
        float a = S0[i * LDN + j] * invN;
        S0[i * LDN + j] = a;
        float zy = 0.5f * (((i == j) ? 3.f : 0.f) - a);
        S3[i * LDN + j] = zy;   // ZY
        S2[i * LDN + j] = zy;   // Z = ZY
    }
    __syncthreads();

    mm64(S1, S0, S3, tx, ty, 0);   // Y = A @ ZY

    float* pY = S1; float* pZ = S2; float* pT = S0; float* pU = S3;
    for (int it = 0; it < 3; it++) {
        mm64(pT, pZ, pY, tx, ty, 1);   // T = 0.5(3I - Z@Y) = ZYnew
        mm64(pU, pY, pT, tx, ty, 0);   // U = Ynew = Y @ ZYnew
        mm64(pY, pT, pZ, tx, ty, 0);   // (Y slot) = Znew = ZYnew @ Z
        float* oY = pY; float* oZ = pZ; float* oT = pT; float* oU = pU;
        pY = oU; pZ = oY; pT = oT; pU = oZ;
    }

    // Final: y_vec = (0.5/64)*sqrt(normA) * (3u - (u^T Z) Y), u = colsum(Y)
    if (t < 64) {
        float u = 0.f;
        for (int i = 0; i < 64; i++) u += pY[i * LDN + t];
        svec[t] = u;
    }
    __syncthreads();
    if (t < 64) {
        float v = 0.f;
        for (int i = 0; i < 64; i++) v += svec[i] * pZ[i * LDN + t];
        vvec[t] = v;
    }
    __syncthreads();
    if (t < 64) {
        float w = 0.f;
        for (int k = 0; k < 64; k++) w += vvec[k] * pY[k * LDN + t];
        float c = (0.5f / 64.f) * sqrtf(snorm);
        svec[t] = c * (3.f * svec[t] - w);   // y_vec
    }
    __syncthreads();
    // conv1 center tap + bias + relu
    if (t < 64) {
        float a = b1[t];
        for (int i = 0; i < 64; i++) a += w1[(t * 64 + i) * 9 + 4] * svec[i];
        vvec[t] = fmaxf(a, 0.f);
    }
    __syncthreads();
    // conv2 center tap + bias + sigmoid
    if (t < 64) {
        float a = b2[t];
        for (int i = 0; i < 64; i++) a += w2[(t * 64 + i) * 9 + 4] * vvec[i];
        g_scale[b * 64 + t] = 1.f / (1.f + expf(-a));
    }
}

// ---------------------------------------------------------------------------
// Kernel 4: out = scale[b,c] * x   (float4, HBM-bound)
// ---------------------------------------------------------------------------
__global__ __launch_bounds__(256) void scale_kernel(const float4* __restrict__ x4,
                                                    float4* __restrict__ out4) {
    int i = blockIdx.x * 256 + threadIdx.x;
    float s = g_scale[i >> 10];   // 4096 floats = 1024 float4 per (b,c)
    float4 v = x4[i];
    v.x *= s; v.y *= s; v.z *= s; v.w *= s;
    out4[i] = v;
}

extern "C" void kernel_launch(void* const* d_in, const int* in_sizes, int n_in,
                              void* d_out, int out_size) {
    const float* x  = (const float*)d_in[0];
    const float* w1 = (const float*)d_in[1];
    const float* b1 = (const float*)d_in[2];
    const float* w2 = (const float*)d_in[3];
    const float* b2 = (const float*)d_in[4];
    float* out = (float*)d_out;

    (void)in_sizes; (void)n_in; (void)out_size;

    const int ns_smem = 4 * 64 * LDN * (int)sizeof(float);
    cudaFuncSetAttribute(ns_kernel, cudaFuncAttributeMaxDynamicSharedMemorySize, ns_smem);

    dim3 gcov(NSPLIT, BATCH);
    cov_kernel<<<gcov, 64>>>(x);
    reduce_kernel<<<BATCH * CC * CC / 256, 256>>>();
    ns_kernel<<<BATCH, 256, ns_smem>>>(w1, b1, w2, b2);
    scale_kernel<<<(BATCH * CC * MM / 4) / 256, 256>>>((const float4*)x, (float4*)out);
}

// round 3
// speedup vs baseline: 1.0717x; 1.0717x over previous
#include <cuda_runtime.h>
#include <math.h>

#define BATCH  16
#define CC     64
#define MM     4096
#define NSPLIT 64          // one 64-col tile per block -> 1024 blocks
#define LDAU   34          // ull stride per k-row (32 pairs + pad, keeps 16B align)
#define LDAF   (2*LDAU)    // float view stride = 68
#define LDN    68          // ns smem row stride

typedef unsigned long long ull;

__device__ __forceinline__ ull pack2(float lo, float hi) {
    ull r; asm("mov.b64 %0,{%1,%2};" : "=l"(r) : "f"(lo), "f"(hi)); return r;
}
__device__ __forceinline__ void unpack2(ull v, float& lo, float& hi) {
    asm("mov.b64 {%0,%1},%2;" : "=f"(lo), "=f"(hi) : "l"(v));
}
__device__ __forceinline__ ull fma2(ull a, ull b, ull c) {
    ull d; asm("fma.rn.f32x2 %0,%1,%2,%3;" : "=l"(d) : "l"(a), "l"(b), "l"(c)); return d;
}

// Deterministic scratch (no float atomics)
__device__ float g_part[BATCH * NSPLIT * CC * CC];   // 16 MB partial Grams (L2-resident)
__device__ float g_rspart[BATCH * NSPLIT * CC];
__device__ float g_cov[BATCH * CC * CC];
__device__ float g_scale[BATCH * CC];

// ---------------------------------------------------------------------------
// Kernel 1: partial X·X^T per (batch, 64-col split) + partial row sums.
// grid (NSPLIT, BATCH) = 1024 blocks, 128 threads (4 warps).
// smem: bufA[k][p] = pack(x[2p][k], x[2p+1][k]) -> A reads are ull2 (no dups),
// B reads are scalar floats from the float view of the same buffer.
// Thread tile: 8 rows (4 packed pairs) x 4 cols. 16 FFMA2 per k.
// ---------------------------------------------------------------------------
__global__ __launch_bounds__(128) void cov_kernel(const float* __restrict__ x) {
    __shared__ ull bufA[64 * LDAU];
    float* bufF = (float*)bufA;

    const int split = blockIdx.x, b = blockIdx.y;
    const int t = threadIdx.x;
    const int tx = t & 15;       // col group (4 cols)
    const int tyr = t >> 4;      // row-of-8 during load; also rowgroup in FMA
    const float* xb = x + (size_t)b * CC * MM + (size_t)split * 64;

    // ---- load 64x64 tile: 8 LDG.128 per thread, then transposed scalar STS ----
    float4 v[8];
#pragma unroll
    for (int it = 0; it < 8; it++) {
        int row = it * 8 + tyr;
        v[it] = *(const float4*)&xb[(size_t)row * MM + 4 * tx];
    }
#pragma unroll
    for (int it = 0; it < 8; it++) {
        int row = it * 8 + tyr;
        bufF[(4 * tx + 0) * LDAF + row] = v[it].x;
        bufF[(4 * tx + 1) * LDAF + row] = v[it].y;
        bufF[(4 * tx + 2) * LDAF + row] = v[it].z;
        bufF[(4 * tx + 3) * LDAF + row] = v[it].w;
    }
    __syncthreads();

    // ---- rank-64 Gram update ----
    ull acc[4][4];
#pragma unroll
    for (int p = 0; p < 4; p++)
#pragma unroll
        for (int j = 0; j < 4; j++) acc[p][j] = 0ull;

    const ull*   Abase = bufA + 4 * tyr;     // pairs 4*tyr .. 4*tyr+3
    const float* Bbase = bufF + 4 * tx;      // cols 4*tx .. 4*tx+3

#pragma unroll 4
    for (int k = 0; k < 64; k++) {
        ulonglong2 a01 = *(const ulonglong2*)(Abase + (size_t)k * LDAU);
        ulonglong2 a23 = *(const ulonglong2*)(Abase + (size_t)k * LDAU + 2);
        const float* Bk = Bbase + k * LDAF;
        ull b0 = pack2(Bk[0], Bk[0]);
        ull b1 = pack2(Bk[1], Bk[1]);
        ull b2 = pack2(Bk[2], Bk[2]);
        ull b3 = pack2(Bk[3], Bk[3]);
        acc[0][0] = fma2(a01.x, b0, acc[0][0]);
        acc[0][1] = fma2(a01.x, b1, acc[0][1]);
        acc[0][2] = fma2(a01.x, b2, acc[0][2]);
        acc[0][3] = fma2(a01.x, b3, acc[0][3]);
        acc[1][0] = fma2(a01.y, b0, acc[1][0]);
        acc[1][1] = fma2(a01.y, b1, acc[1][1]);
        acc[1][2] = fma2(a01.y, b2, acc[1][2]);
        acc[1][3] = fma2(a01.y, b3, acc[1][3]);
        acc[2][0] = fma2(a23.x, b0, acc[2][0]);
        acc[2][1] = fma2(a23.x, b1, acc[2][1]);
        acc[2][2] = fma2(a23.x, b2, acc[2][2]);
        acc[2][3] = fma2(a23.x, b3, acc[2][3]);
        acc[3][0] = fma2(a23.y, b0, acc[3][0]);
        acc[3][1] = fma2(a23.y, b1, acc[3][1]);
        acc[3][2] = fma2(a23.y, b2, acc[3][2]);
        acc[3][3] = fma2(a23.y, b3, acc[3][3]);
    }

    // ---- epilogue: write 8x4 tile of partial Gram ----
    float* P = g_part + (((size_t)(b * NSPLIT + split)) << 12);
#pragma unroll
    for (int p = 0; p < 4; p++)
#pragma unroll
        for (int j = 0; j < 4; j++) {
            float lo, hi; unpack2(acc[p][j], lo, hi);
            int col = 4 * tx + j;
            P[(8 * tyr + 2 * p)     * 64 + col] = lo;
            P[(8 * tyr + 2 * p + 1) * 64 + col] = hi;
        }

    // ---- partial row sums (bufF unchanged; conflict-free: (4k+j)%32 distinct) ----
    if (t < 64) {
        float s = 0.f;
#pragma unroll 16
        for (int k = 0; k < 64; k++) s += bufF[k * LDAF + t];
        g_rspart[(b * NSPLIT + split) * 64 + t] = s;
    }
}

// ---------------------------------------------------------------------------
// Kernel 2: reduce partial Grams across splits (fully parallel, L2-bound).
// ---------------------------------------------------------------------------
__global__ __launch_bounds__(256) void reduce_kernel() {
    int idx = blockIdx.x * 256 + threadIdx.x;       // 0 .. 16*4096-1
    int b = idx >> 12, e = idx & 4095;
    float s = 0.f;
#pragma unroll
    for (int sp = 0; sp < NSPLIT; sp++)
        s += g_part[(((size_t)(b * NSPLIT + sp)) << 12) + e];
    g_cov[idx] = s;
}

// ---------------------------------------------------------------------------
// 64x64x64 smem matmul, f32x2. 256 threads, 1 row x 16 cols per thread.
// mode 0: C = A@B ; mode 1: C = 0.5*(3I - A@B)
// ---------------------------------------------------------------------------
__device__ __forceinline__ void mm64(float* __restrict__ C, const float* __restrict__ A,
                                     const float* __restrict__ B, int tx, int ty, int mode) {
    ull acc[8];
#pragma unroll
    for (int c = 0; c < 8; c++) acc[c] = 0ull;

    const float* Arow = A + ty * LDN;
    const float* Bc = B + 16 * tx;

#pragma unroll 8
    for (int k = 0; k < 64; k++) {
        float a = Arow[k];
        ull da = pack2(a, a);
        const ulonglong2* bp = (const ulonglong2*)(Bc + k * LDN);
        ulonglong2 q0 = bp[0], q1 = bp[1], q2 = bp[2], q3 = bp[3];
        acc[0] = fma2(da, q0.x, acc[0]); acc[1] = fma2(da, q0.y, acc[1]);
        acc[2] = fma2(da, q1.x, acc[2]); acc[3] = fma2(da, q1.y, acc[3]);
        acc[4] = fma2(da, q2.x, acc[4]); acc[5] = fma2(da, q2.y, acc[5]);
        acc[6] = fma2(da, q3.x, acc[6]); acc[7] = fma2(da, q3.y, acc[7]);
    }
    __syncthreads();   // all operand reads done before C overwrites anything
#pragma unroll
    for (int c = 0; c < 8; c++) {
        float lo, hi; unpack2(acc[c], lo, hi);
        int j = 16 * tx + 2 * c;
        if (mode) {
            lo = 0.5f * (((ty == j)     ? 3.f : 0.f) - lo);
            hi = 0.5f * (((ty == j + 1) ? 3.f : 0.f) - hi);
        }
        *(float2*)&C[ty * LDN + j] = make_float2(lo, hi);
    }
    __syncthreads();   // C visible
}

// ---------------------------------------------------------------------------
// Kernel 3: covariance assembly + Newton-Schulz + center-tap convs.
// 16 blocks x 256 threads. Dynamic smem: 4 matrices [64][LDN].
// ---------------------------------------------------------------------------
__global__ __launch_bounds__(256) void ns_kernel(const float* __restrict__ w1, const float* __restrict__ b1,
                                                 const float* __restrict__ w2, const float* __restrict__ b2) {
    extern __shared__ float sm[];
    float* S0 = sm;
    float* S1 = sm + 64 * LDN;
    float* S2 = sm + 2 * 64 * LDN;
    float* S3 = sm + 3 * 64 * LDN;
    __shared__ float svec[64];
    __shared__ float vvec[64];
    __shared__ float red[8];
    __shared__ float snorm;

    const int b = blockIdx.x, t = threadIdx.x;
    const int tx = t & 3, ty = t >> 2;
    const float invM = 1.0f / (float)MM;
    const float invM2 = invM * invM;

    // row sums
    if (t < 64) {
        float s = 0.f;
        for (int sp = 0; sp < NSPLIT; sp++) s += g_rspart[(b * NSPLIT + sp) * 64 + t];
        svec[t] = s;
    }
    __syncthreads();

    // cov = Sxx/M - s s^T / M^2 ; normA = sum(cov)
    float lsum = 0.f;
#pragma unroll
    for (int e = 0; e < 16; e++) {
        int idx = e * 256 + t;
        int i = idx >> 6, j = idx & 63;
        float cv = invM * g_cov[b * 4096 + idx] - invM2 * svec[i] * svec[j];
        S0[i * LDN + j] = cv;
        lsum += cv;
    }
#pragma unroll
    for (int o = 16; o; o >>= 1) lsum += __shfl_xor_sync(0xffffffffu, lsum, o);
    if ((t & 31) == 0) red[t >> 5] = lsum;
    __syncthreads();
    if (t == 0) { float s = 0.f; for (int w = 0; w < 8; w++) s += red[w]; snorm = s; }
    __syncthreads();

    const float invN = 1.f / snorm;
#pragma unroll
    for (int e = 0; e < 16; e++) {
        int idx = e * 256 + t;
        int i = idx >> 6, j = idx & 63;
        float a = S0[i * LDN + j] * invN;
        S0[i * LDN + j] = a;
        float zy = 0.5f * (((i == j) ? 3.f : 0.f) - a);
        S3[i * LDN + j] = zy;   // ZY
        S2[i * LDN + j] = zy;   // Z = ZY
    }
    __syncthreads();

    mm64(S1, S0, S3, tx, ty, 0);   // Y = A @ ZY

    float* pY = S1; float* pZ = S2; float* pT = S0; float* pU = S3;
    for (int it = 0; it < 3; it++) {
        mm64(pT, pZ, pY, tx, ty, 1);   // T = 0.5(3I - Z@Y) = ZYnew
        mm64(pU, pY, pT, tx, ty, 0);   // U = Ynew = Y @ ZYnew
        mm64(pY, pT, pZ, tx, ty, 0);   // (Y slot) = Znew = ZYnew @ Z
        float* oY = pY; float* oZ = pZ; float* oT = pT; float* oU = pU;
        pY = oU; pZ = oY; pT = oT; pU = oZ;
    }

    // Final: y_vec = (0.5/64)*sqrt(normA) * (3u - (u^T Z) Y), u = colsum(Y)
    if (t < 64) {
        float u = 0.f;
        for (int i = 0; i < 64; i++) u += pY[i * LDN + t];
        svec[t] = u;
    }
    __syncthreads();
    if (t < 64) {
        float vv = 0.f;
        for (int i = 0; i < 64; i++) vv += svec[i] * pZ[i * LDN + t];
        vvec[t] = vv;
    }
    __syncthreads();
    if (t < 64) {
        float w = 0.f;
        for (int k = 0; k < 64; k++) w += vvec[k] * pY[k * LDN + t];
        float c = (0.5f / 64.f) * sqrtf(snorm);
        svec[t] = c * (3.f * svec[t] - w);   // y_vec
    }
    __syncthreads();
    // conv1 center tap + bias + relu
    if (t < 64) {
        float a = b1[t];
        for (int i = 0; i < 64; i++) a += w1[(t * 64 + i) * 9 + 4] * svec[i];
        vvec[t] = fmaxf(a, 0.f);
    }
    __syncthreads();
    // conv2 center tap + bias + sigmoid
    if (t < 64) {
        float a = b2[t];
        for (int i = 0; i < 64; i++) a += w2[(t * 64 + i) * 9 + 4] * vvec[i];
        g_scale[b * 64 + t] = 1.f / (1.f + expf(-a));
    }
}

// ---------------------------------------------------------------------------
// Kernel 4: out = scale[b,c] * x.  8 float4 per thread, batched loads (MLP=8).
// ---------------------------------------------------------------------------
__global__ __launch_bounds__(256) void scale_kernel(const float4* __restrict__ x4,
                                                    float4* __restrict__ out4) {
    int base = blockIdx.x * 2048 + threadIdx.x;
    float4 v[8];
    float  s[8];
#pragma unroll
    for (int j = 0; j < 8; j++) {
        int i = base + j * 256;
        v[j] = __ldg(&x4[i]);
        s[j] = g_scale[i >> 10];   // 1024 float4 per (b,c)
    }
#pragma unroll
    for (int j = 0; j < 8; j++) {
        int i = base + j * 256;
        float4 o = v[j];
        o.x *= s[j]; o.y *= s[j]; o.z *= s[j]; o.w *= s[j];
        out4[i] = o;
    }
}

extern "C" void kernel_launch(void* const* d_in, const int* in_sizes, int n_in,
                              void* d_out, int out_size) {
    const float* x  = (const float*)d_in[0];
    const float* w1 = (const float*)d_in[1];
    const float* b1 = (const float*)d_in[2];
    const float* w2 = (const float*)d_in[3];
    const float* b2 = (const float*)d_in[4];
    float* out = (float*)d_out;

    (void)in_sizes; (void)n_in; (void)out_size;

    const int ns_smem = 4 * 64 * LDN * (int)sizeof(float);
    cudaFuncSetAttribute(ns_kernel, cudaFuncAttributeMaxDynamicSharedMemorySize, ns_smem);

    dim3 gcov(NSPLIT, BATCH);
    cov_kernel<<<gcov, 128>>>(x);
    reduce_kernel<<<BATCH * CC * CC / 256, 256>>>();
    ns_kernel<<<BATCH, 256, ns_smem>>>(w1, b1, w2, b2);
    scale_kernel<<<(BATCH * CC * MM / 4) / 2048, 256>>>((const float4*)x, (float4*)out);
}

// round 4
// speedup vs baseline: 2.2554x; 2.1045x over previous
#include <cuda_runtime.h>
#include <math.h>

#define BATCH  16
#define CC     64
#define MM     4096
#define NSPLIT 64     // one 64-col tile per block -> 1024 blocks
#define LDP    68     // padded smem row stride (floats): float4-aligned reads

// Deterministic scratch (no float atomics)
__device__ float g_part[BATCH * NSPLIT * CC * CC];   // 16 MB partial Grams (L2-resident)
__device__ float g_rspart[BATCH * NSPLIT * CC];
__device__ float g_cov[BATCH * CC * CC];
__device__ float g_scale[BATCH * CC];

// ---------------------------------------------------------------------------
// Kernel 1: partial X·X^T per (batch, 64-col tile) + partial row sums.
// grid (NSPLIT, BATCH) = 1024 blocks, 256 threads. R1-proven inner loop:
// smem tile transposed buf[k][row], each thread owns a 4x4 tile (16 FFMA/k).
// ---------------------------------------------------------------------------
__global__ __launch_bounds__(256) void cov_kernel(const float* __restrict__ x) {
    __shared__ float buf[64 * LDP];
    const int split = blockIdx.x, b = blockIdx.y;
    const int t = threadIdx.x;
    const int tx = t & 15, ty = t >> 4;
    const float* xb = x + (size_t)b * CC * MM + (size_t)split * 64;

    // Load 64 rows x 64 cols, transposed into buf[k][row]; coalesced global reads.
#pragma unroll
    for (int j = 0; j < 16; j++) {
        int idx = j * 256 + t;
        int row = idx >> 6, k = idx & 63;
        buf[k * LDP + row] = xb[(size_t)row * MM + k];
    }
    __syncthreads();

    // Partial row sums: thread t covers row (t&63), k-quarter (t>>6).
    float rs;
    {
        int row = t & 63, k0 = (t >> 6) * 16;
        float s = 0.f;
#pragma unroll
        for (int kc = 0; kc < 16; kc++) s += buf[(k0 + kc) * LDP + row];
        rs = s;
    }

    // Rank-64 Gram update: 4x4 tile per thread.
    float acc[4][4];
#pragma unroll
    for (int r = 0; r < 4; r++)
#pragma unroll
        for (int c = 0; c < 4; c++) acc[r][c] = 0.f;

#pragma unroll 16
    for (int k = 0; k < 64; k++) {
        float4 a4 = *(const float4*)&buf[k * LDP + 4 * ty];
        float4 b4 = *(const float4*)&buf[k * LDP + 4 * tx];
        acc[0][0] += a4.x * b4.x; acc[0][1] += a4.x * b4.y;
        acc[0][2] += a4.x * b4.z; acc[0][3] += a4.x * b4.w;
        acc[1][0] += a4.y * b4.x; acc[1][1] += a4.y * b4.y;
        acc[1][2] += a4.y * b4.z; acc[1][3] += a4.y * b4.w;
        acc[2][0] += a4.z * b4.x; acc[2][1] += a4.z * b4.y;
        acc[2][2] += a4.z * b4.z; acc[2][3] += a4.z * b4.w;
        acc[3][0] += a4.w * b4.x; acc[3][1] += a4.w * b4.y;
        acc[3][2] += a4.w * b4.z; acc[3][3] += a4.w * b4.w;
    }

    float* P = g_part + (((size_t)(b * NSPLIT + split)) << 12);
#pragma unroll
    for (int r = 0; r < 4; r++)
#pragma unroll
        for (int c = 0; c < 4; c++)
            P[(4 * ty + r) * 64 + 4 * tx + c] = acc[r][c];

    // Row-sum partial reduction (reuse buf after all reads are done).
    __syncthreads();
    buf[t] = rs;
    __syncthreads();
    if (t < 64) {
        float s = buf[t] + buf[t + 64] + buf[t + 128] + buf[t + 192];
        g_rspart[(b * NSPLIT + split) * 64 + t] = s;
    }
}

// ---------------------------------------------------------------------------
// Kernel 2: reduce partial Grams across splits (fully parallel, L2-bound).
// ---------------------------------------------------------------------------
__global__ __launch_bounds__(256) void reduce_kernel() {
    int idx = blockIdx.x * 256 + threadIdx.x;       // 0 .. 16*4096-1
    int b = idx >> 12, e = idx & 4095;
    float s = 0.f;
#pragma unroll
    for (int sp = 0; sp < NSPLIT; sp++)
        s += g_part[(((size_t)(b * NSPLIT + sp)) << 12) + e];
    g_cov[idx] = s;
}

// ---------------------------------------------------------------------------
// 64x64x64 smem matmul: C = A@B (mode 0) or C = 0.5*(3I - A@B) (mode 1).
// 256 threads, 4x4 tiles (R1-proven pattern).
// Precondition: operands visible. Postcondition: C visible.
// ---------------------------------------------------------------------------
__device__ __forceinline__ void mm64(float* __restrict__ Cm, const float* __restrict__ A,
                                     const float* __restrict__ Bm, int tx, int ty, int mode) {
    float acc[4][4];
#pragma unroll
    for (int r = 0; r < 4; r++)
#pragma unroll
        for (int c = 0; c < 4; c++) acc[r][c] = 0.f;

    const float* A0 = A + (4 * ty + 0) * LDP;
    const float* A1 = A + (4 * ty + 1) * LDP;
    const float* A2 = A + (4 * ty + 2) * LDP;
    const float* A3 = A + (4 * ty + 3) * LDP;

#pragma unroll 8
    for (int k = 0; k < 64; k++) {
        float a0 = A0[k], a1 = A1[k], a2 = A2[k], a3 = A3[k];
        float4 b4 = *(const float4*)&Bm[k * LDP + 4 * tx];
        acc[0][0] += a0 * b4.x; acc[0][1] += a0 * b4.y; acc[0][2] += a0 * b4.z; acc[0][3] += a0 * b4.w;
        acc[1][0] += a1 * b4.x; acc[1][1] += a1 * b4.y; acc[1][2] += a1 * b4.z; acc[1][3] += a1 * b4.w;
        acc[2][0] += a2 * b4.x; acc[2][1] += a2 * b4.y; acc[2][2] += a2 * b4.z; acc[2][3] += a2 * b4.w;
        acc[3][0] += a3 * b4.x; acc[3][1] += a3 * b4.y; acc[3][2] += a3 * b4.z; acc[3][3] += a3 * b4.w;
    }
    __syncthreads();   // all operand reads done before C overwrites anything
#pragma unroll
    for (int r = 0; r < 4; r++)
#pragma unroll
        for (int c = 0; c < 4; c++) {
            float v = acc[r][c];
            if (mode) {
                int i = 4 * ty + r, j = 4 * tx + c;
                v = 0.5f * (((i == j) ? 3.f : 0.f) - v);
            }
            Cm[(4 * ty + r) * LDP + 4 * tx + c] = v;
        }
    __syncthreads();   // C visible
}

// ---------------------------------------------------------------------------
// Kernel 3: covariance assembly + Newton-Schulz + center-tap convs.
// 16 blocks x 256 threads. Dynamic smem: 4 matrices [64][LDP].
// ---------------------------------------------------------------------------
__global__ __launch_bounds__(256) void ns_kernel(const float* __restrict__ w1, const float* __restrict__ b1,
                                                 const float* __restrict__ w2, const float* __restrict__ b2) {
    extern __shared__ float sm[];
    float* S0 = sm;
    float* S1 = sm + 64 * LDP;
    float* S2 = sm + 2 * 64 * LDP;
    float* S3 = sm + 3 * 64 * LDP;
    __shared__ float svec[64];
    __shared__ float vvec[64];
    __shared__ float red[8];
    __shared__ float snorm;

    const int b = blockIdx.x, t = threadIdx.x;
    const int tx = t & 15, ty = t >> 4;
    const float invM = 1.0f / (float)MM;
    const float invM2 = invM * invM;

    // row sums
    if (t < 64) {
        float s = 0.f;
        for (int sp = 0; sp < NSPLIT; sp++) s += g_rspart[(b * NSPLIT + sp) * 64 + t];
        svec[t] = s;
    }
    __syncthreads();

    // cov = Sxx/M - s s^T / M^2 ; normA = sum(cov)
    float lsum = 0.f;
#pragma unroll
    for (int e = 0; e < 16; e++) {
        int idx = e * 256 + t;
        int i = idx >> 6, j = idx & 63;
        float cv = invM * g_cov[b * 4096 + idx] - invM2 * svec[i] * svec[j];
        S0[i * LDP + j] = cv;
        lsum += cv;
    }
#pragma unroll
    for (int o = 16; o; o >>= 1) lsum += __shfl_xor_sync(0xffffffffu, lsum, o);
    if ((t & 31) == 0) red[t >> 5] = lsum;
    __syncthreads();
    if (t == 0) { float s = 0.f; for (int w = 0; w < 8; w++) s += red[w]; snorm = s; }
    __syncthreads();

    const float invN = 1.f / snorm;
#pragma unroll
    for (int e = 0; e < 16; e++) {
        int idx = e * 256 + t;
        int i = idx >> 6, j = idx & 63;
        float a = S0[i * LDP + j] * invN;
        S0[i * LDP + j] = a;
        float zy = 0.5f * (((i == j) ? 3.f : 0.f) - a);
        S3[i * LDP + j] = zy;   // ZY
        S2[i * LDP + j] = zy;   // Z = ZY
    }
    __syncthreads();

    mm64(S1, S0, S3, tx, ty, 0);   // Y = A @ ZY

    float* pY = S1; float* pZ = S2; float* pT = S0; float* pU = S3;
    for (int it = 0; it < 3; it++) {
        mm64(pT, pZ, pY, tx, ty, 1);   // T = 0.5(3I - Z@Y) = ZYnew
        mm64(pU, pY, pT, tx, ty, 0);   // U = Ynew = Y @ ZYnew
        mm64(pY, pT, pZ, tx, ty, 0);   // (old Y slot) = Znew = ZYnew @ Z
        float* oY = pY; float* oZ = pZ; float* oT = pT; float* oU = pU;
        pY = oU; pZ = oY; pT = oT; pU = oZ;
    }

    // Stage conv center taps into the two dead smem matrices (parallel loads).
    // pT and pU are free now (pT last held ZY, pU last held stale Z).
    float* W1 = pT;   // 4096 floats fit: 64*LDP >= 4096
    float* W2 = pU;
#pragma unroll
    for (int e = 0; e < 16; e++) {
        int n = e * 256 + t;                 // n = outc*64 + inc
        W1[n] = w1[n * 9 + 4];
        W2[n] = w2[n * 9 + 4];
    }
    // (no sync needed yet; tail below syncs before use)

    // y_vec = (0.5/64)*sqrt(normA) * (3u - (u^T Z) Y), u = colsum(Y)
    __syncthreads();
    if (t < 64) {
        float u = 0.f;
        for (int i = 0; i < 64; i++) u += pY[i * LDP + t];
        svec[t] = u;
    }
    __syncthreads();
    if (t < 64) {
        float vv = 0.f;
        for (int i = 0; i < 64; i++) vv += svec[i] * pZ[i * LDP + t];
        vvec[t] = vv;
    }
    __syncthreads();
    if (t < 64) {
        float w = 0.f;
        for (int k = 0; k < 64; k++) w += vvec[k] * pY[k * LDP + t];
        float c = (0.5f / 64.f) * sqrtf(snorm);
        svec[t] = c * (3.f * svec[t] - w);   // y_vec
    }
    __syncthreads();
    // conv1 center tap + bias + relu
    if (t < 64) {
        float a = b1[t];
        for (int i = 0; i < 64; i++) a += W1[t * 64 + i] * svec[i];
        vvec[t] = fmaxf(a, 0.f);
    }
    __syncthreads();
    // conv2 center tap + bias + sigmoid
    if (t < 64) {
        float a = b2[t];
        for (int i = 0; i < 64; i++) a += W2[t * 64 + i] * vvec[i];
        g_scale[b * 64 + t] = 1.f / (1.f + expf(-a));
    }
}

// ---------------------------------------------------------------------------
// Kernel 4: out = scale[b,c] * x.  8 float4 per thread, batched loads (MLP=8).
// ---------------------------------------------------------------------------
__global__ __launch_bounds__(256) void scale_kernel(const float4* __restrict__ x4,
                                                    float4* __restrict__ out4) {
    int base = blockIdx.x * 2048 + threadIdx.x;
    float4 v[8];
    float  s[8];
#pragma unroll
    for (int j = 0; j < 8; j++) {
        int i = base + j * 256;
        v[j] = __ldg(&x4[i]);
        s[j] = g_scale[i >> 10];   // 1024 float4 per (b,c)
    }
#pragma unroll
    for (int j = 0; j < 8; j++) {
        int i = base + j * 256;
        float4 o = v[j];
        o.x *= s[j]; o.y *= s[j]; o.z *= s[j]; o.w *= s[j];
        out4[i] = o;
    }
}

extern "C" void kernel_launch(void* const* d_in, const int* in_sizes, int n_in,
                              void* d_out, int out_size) {
    const float* x  = (const float*)d_in[0];
    const float* w1 = (const float*)d_in[1];
    const float* b1 = (const float*)d_in[2];
    const float* w2 = (const float*)d_in[3];
    const float* b2 = (const float*)d_in[4];
    float* out = (float*)d_out;

    (void)in_sizes; (void)n_in; (void)out_size;

    const int ns_smem = 4 * 64 * LDP * (int)sizeof(float);
    cudaFuncSetAttribute(ns_kernel, cudaFuncAttributeMaxDynamicSharedMemorySize, ns_smem);

    dim3 gcov(NSPLIT, BATCH);
    cov_kernel<<<gcov, 256>>>(x);
    reduce_kernel<<<BATCH * CC * CC / 256, 256>>>();
    ns_kernel<<<BATCH, 256, ns_smem>>>(w1, b1, w2, b2);
    scale_kernel<<<(BATCH * CC * MM / 4) / 2048, 256>>>((const float4*)x, (float4*)out);
}

// round 5
// speedup vs baseline: 2.5141x; 1.1147x over previous
#include <cuda_runtime.h>
#include <math.h>

#define BATCH  16
#define CC     64
#define MM     4096
#define NSPLIT 8      // 512-col chunk per block -> 128 blocks
#define CHUNK  512
#define LDS    68     // smem row stride (words); 68 % 32 == 4 -> conflict-free frags
#define LDP    68     // ns smem row stride

// Deterministic scratch (no float atomics)
__device__ float g_part[BATCH * NSPLIT * CC * CC];   // 2 MB partial Grams (L2-resident)
__device__ float g_rspart[BATCH * NSPLIT * CC];
__device__ float g_cov[BATCH * CC * CC];
__device__ float g_scale[BATCH * CC];

__device__ __forceinline__ unsigned cvt_tf32(float f) {
    unsigned r; asm("cvt.rna.tf32.f32 %0, %1;" : "=r"(r) : "f"(f)); return r;
}
__device__ __forceinline__ void mma_tf32(float c[4], unsigned a0, unsigned a1,
                                         unsigned a2, unsigned a3,
                                         unsigned b0, unsigned b1) {
    asm("mma.sync.aligned.m16n8k8.row.col.f32.tf32.tf32.f32 "
        "{%0,%1,%2,%3},{%4,%5,%6,%7},{%8,%9},{%0,%1,%2,%3};"
        : "+f"(c[0]), "+f"(c[1]), "+f"(c[2]), "+f"(c[3])
        : "r"(a0), "r"(a1), "r"(a2), "r"(a3), "r"(b0), "r"(b1));
}

// ---------------------------------------------------------------------------
// Kernel 1: partial X·X^T per (batch, 512-col chunk) via tf32 mma.sync,
// + fp32 partial row sums. grid (NSPLIT, BATCH) = 128 blocks, 256 threads.
// tf32 conversion happens once at the smem store; inner loop = LDS + MMA.
// Warp w: rows [16*(w&3), +16), cols [32*(w>>2), +32)  (4 n8-tiles per warp).
// ---------------------------------------------------------------------------
__global__ __launch_bounds__(256) void cov_kernel(const float* __restrict__ x) {
    __shared__ unsigned buf[64 * LDS];
    const int split = blockIdx.x, b = blockIdx.y;
    const int t = threadIdx.x;
    const int lane = t & 31, w = t >> 5;
    const int m0 = 16 * (w & 3);
    const int n0base = 32 * (w >> 2);
    const int g = lane >> 2, tg = lane & 3;
    const int lrow = t >> 4, lcg = t & 15;
    const float* xb = x + (size_t)b * CC * MM + (size_t)split * CHUNK;

    float c[4][4];
#pragma unroll
    for (int j = 0; j < 4; j++)
#pragma unroll
        for (int q = 0; q < 4; q++) c[j][q] = 0.f;
    float rs[4] = {0.f, 0.f, 0.f, 0.f};

    for (int kb = 0; kb < CHUNK / 64; kb++) {
        __syncthreads();
        // Load 64x64 fp32 sub-tile, accumulate fp32 row sums, store tf32 bits.
#pragma unroll
        for (int j = 0; j < 4; j++) {
            int row = j * 16 + lrow;
            float4 v = *(const float4*)&xb[(size_t)row * MM + kb * 64 + 4 * lcg];
            rs[j] += (v.x + v.y) + (v.z + v.w);
            uint4 u;
            u.x = cvt_tf32(v.x); u.y = cvt_tf32(v.y);
            u.z = cvt_tf32(v.z); u.w = cvt_tf32(v.w);
            *(uint4*)&buf[row * LDS + 4 * lcg] = u;
        }
        __syncthreads();
        // 8 k-steps of m16n8k8; all frag loads conflict-free (LDS%32==4).
#pragma unroll
        for (int k0 = 0; k0 < 64; k0 += 8) {
            unsigned a0 = buf[(m0 + g) * LDS + k0 + tg];
            unsigned a1 = buf[(m0 + g + 8) * LDS + k0 + tg];
            unsigned a2 = buf[(m0 + g) * LDS + k0 + tg + 4];
            unsigned a3 = buf[(m0 + g + 8) * LDS + k0 + tg + 4];
#pragma unroll
            for (int j = 0; j < 4; j++) {
                int n0 = n0base + 8 * j;
                unsigned b0 = buf[(n0 + g) * LDS + k0 + tg];
                unsigned b1 = buf[(n0 + g) * LDS + k0 + tg + 4];
                mma_tf32(c[j], a0, a1, a2, a3, b0, b1);
            }
        }
    }

    // Epilogue: write partial Gram fragments (c0,c1 / c2,c3 are col-adjacent).
    float* P = g_part + (((size_t)(b * NSPLIT + split)) << 12);
#pragma unroll
    for (int j = 0; j < 4; j++) {
        int row = m0 + g, col = n0base + 8 * j + 2 * tg;
        *(float2*)&P[row * 64 + col]       = make_float2(c[j][0], c[j][1]);
        *(float2*)&P[(row + 8) * 64 + col] = make_float2(c[j][2], c[j][3]);
    }

    // Row sums: reduce 16 per-colgroup partials per row via smem scratch.
    __syncthreads();
    float* rsm = (float*)buf;
#pragma unroll
    for (int j = 0; j < 4; j++)
        rsm[(j * 16 + lrow) * 17 + lcg] = rs[j];
    __syncthreads();
    if (t < 64) {
        float s = 0.f;
#pragma unroll
        for (int i = 0; i < 16; i++) s += rsm[t * 17 + i];
        g_rspart[(b * NSPLIT + split) * 64 + t] = s;
    }
}

// ---------------------------------------------------------------------------
// Kernel 2: reduce partial Grams across splits (fully parallel, L2-bound).
// ---------------------------------------------------------------------------
__global__ __launch_bounds__(256) void reduce_kernel() {
    int idx = blockIdx.x * 256 + threadIdx.x;       // 0 .. 16*4096-1
    int b = idx >> 12, e = idx & 4095;
    float s = 0.f;
#pragma unroll
    for (int sp = 0; sp < NSPLIT; sp++)
        s += g_part[(((size_t)(b * NSPLIT + sp)) << 12) + e];
    g_cov[idx] = s;
}

// ---------------------------------------------------------------------------
// 64x64x64 smem matmul: C = A@B (mode 0) or C = 0.5*(3I - A@B) (mode 1).
// 256 threads, 4x4 tiles (proven R1/R4 pattern).
// ---------------------------------------------------------------------------
__device__ __forceinline__ void mm64(float* __restrict__ Cm, const float* __restrict__ A,
                                     const float* __restrict__ Bm, int tx, int ty, int mode) {
    float acc[4][4];
#pragma unroll
    for (int r = 0; r < 4; r++)
#pragma unroll
        for (int c = 0; c < 4; c++) acc[r][c] = 0.f;

    const float* A0 = A + (4 * ty + 0) * LDP;
    const float* A1 = A + (4 * ty + 1) * LDP;
    const float* A2 = A + (4 * ty + 2) * LDP;
    const float* A3 = A + (4 * ty + 3) * LDP;

#pragma unroll 8
    for (int k = 0; k < 64; k++) {
        float a0 = A0[k], a1 = A1[k], a2 = A2[k], a3 = A3[k];
        float4 b4 = *(const float4*)&Bm[k * LDP + 4 * tx];
        acc[0][0] += a0 * b4.x; acc[0][1] += a0 * b4.y; acc[0][2] += a0 * b4.z; acc[0][3] += a0 * b4.w;
        acc[1][0] += a1 * b4.x; acc[1][1] += a1 * b4.y; acc[1][2] += a1 * b4.z; acc[1][3] += a1 * b4.w;
        acc[2][0] += a2 * b4.x; acc[2][1] += a2 * b4.y; acc[2][2] += a2 * b4.z; acc[2][3] += a2 * b4.w;
        acc[3][0] += a3 * b4.x; acc[3][1] += a3 * b4.y; acc[3][2] += a3 * b4.z; acc[3][3] += a3 * b4.w;
    }
    __syncthreads();   // all operand reads done before C overwrites anything
#pragma unroll
    for (int r = 0; r < 4; r++)
#pragma unroll
        for (int c = 0; c < 4; c++) {
            float v = acc[r][c];
            if (mode) {
                int i = 4 * ty + r, j = 4 * tx + c;
                v = 0.5f * (((i == j) ? 3.f : 0.f) - v);
            }
            Cm[(4 * ty + r) * LDP + 4 * tx + c] = v;
        }
    __syncthreads();   // C visible
}

// ---------------------------------------------------------------------------
// Kernel 3: covariance assembly + Newton-Schulz + center-tap convs.
// 16 blocks x 256 threads. Dynamic smem: 4 matrices [64][LDP].
// ---------------------------------------------------------------------------
__global__ __launch_bounds__(256) void ns_kernel(const float* __restrict__ w1, const float* __restrict__ b1,
                                                 const float* __restrict__ w2, const float* __restrict__ b2) {
    extern __shared__ float sm[];
    float* S0 = sm;
    float* S1 = sm + 64 * LDP;
    float* S2 = sm + 2 * 64 * LDP;
    float* S3 = sm + 3 * 64 * LDP;
    __shared__ float svec[64];
    __shared__ float vvec[64];
    __shared__ float red[8];
    __shared__ float snorm;

    const int b = blockIdx.x, t = threadIdx.x;
    const int tx = t & 15, ty = t >> 4;
    const float invM = 1.0f / (float)MM;
    const float invM2 = invM * invM;

    // row sums
    if (t < 64) {
        float s = 0.f;
#pragma unroll
        for (int sp = 0; sp < NSPLIT; sp++) s += g_rspart[(b * NSPLIT + sp) * 64 + t];
        svec[t] = s;
    }
    __syncthreads();

    // cov = Sxx/M - s s^T / M^2 ; normA = sum(cov)
    float lsum = 0.f;
#pragma unroll
    for (int e = 0; e < 16; e++) {
        int idx = e * 256 + t;
        int i = idx >> 6, j = idx & 63;
        float cv = invM * g_cov[b * 4096 + idx] - invM2 * svec[i] * svec[j];
        S0[i * LDP + j] = cv;
        lsum += cv;
    }
#pragma unroll
    for (int o = 16; o; o >>= 1) lsum += __shfl_xor_sync(0xffffffffu, lsum, o);
    if ((t & 31) == 0) red[t >> 5] = lsum;
    __syncthreads();
    if (t == 0) { float s = 0.f; for (int w = 0; w < 8; w++) s += red[w]; snorm = s; }
    __syncthreads();

    const float invN = 1.f / snorm;
#pragma unroll
    for (int e = 0; e < 16; e++) {
        int idx = e * 256 + t;
        int i = idx >> 6, j = idx & 63;
        float a = S0[i * LDP + j] * invN;
        S0[i * LDP + j] = a;
        float zy = 0.5f * (((i == j) ? 3.f : 0.f) - a);
        S3[i * LDP + j] = zy;   // ZY
        S2[i * LDP + j] = zy;   // Z = ZY
    }
    __syncthreads();

    mm64(S1, S0, S3, tx, ty, 0);   // Y = A @ ZY

    float* pY = S1; float* pZ = S2; float* pT = S0; float* pU = S3;
    for (int it = 0; it < 3; it++) {
        mm64(pT, pZ, pY, tx, ty, 1);   // T = 0.5(3I - Z@Y) = ZYnew
        mm64(pU, pY, pT, tx, ty, 0);   // U = Ynew = Y @ ZYnew
        mm64(pY, pT, pZ, tx, ty, 0);   // (old Y slot) = Znew = ZYnew @ Z
        float* oY = pY; float* oZ = pZ; float* oT = pT; float* oU = pU;
        pY = oU; pZ = oY; pT = oT; pU = oZ;
    }

    // Stage conv center taps into the two dead smem matrices (parallel loads).
    float* W1 = pT;
    float* W2 = pU;
#pragma unroll
    for (int e = 0; e < 16; e++) {
        int n = e * 256 + t;                 // n = outc*64 + inc
        W1[n] = w1[n * 9 + 4];
        W2[n] = w2[n * 9 + 4];
    }

    // y_vec = (0.5/64)*sqrt(normA) * (3u - (u^T Z) Y), u = colsum(Y)
    __syncthreads();
    if (t < 64) {
        float u = 0.f;
        for (int i = 0; i < 64; i++) u += pY[i * LDP + t];
        svec[t] = u;
    }
    __syncthreads();
    if (t < 64) {
        float vv = 0.f;
        for (int i = 0; i < 64; i++) vv += svec[i] * pZ[i * LDP + t];
        vvec[t] = vv;
    }
    __syncthreads();
    if (t < 64) {
        float w = 0.f;
        for (int k = 0; k < 64; k++) w += vvec[k] * pY[k * LDP + t];
        float c = (0.5f / 64.f) * sqrtf(snorm);
        svec[t] = c * (3.f * svec[t] - w);   // y_vec
    }
    __syncthreads();
    // conv1 center tap + bias + relu
    if (t < 64) {
        float a = b1[t];
        for (int i = 0; i < 64; i++) a += W1[t * 64 + i] * svec[i];
        vvec[t] = fmaxf(a, 0.f);
    }
    __syncthreads();
    // conv2 center tap + bias + sigmoid
    if (t < 64) {
        float a = b2[t];
        for (int i = 0; i < 64; i++) a += W2[t * 64 + i] * vvec[i];
        g_scale[b * 64 + t] = 1.f / (1.f + expf(-a));
    }
}

// ---------------------------------------------------------------------------
// Kernel 4: out = scale[b,c] * x. 8 float4/thread; streaming stores (__stcs)
// keep x L2-resident for the reads.
// ---------------------------------------------------------------------------
__global__ __launch_bounds__(256) void scale_kernel(const float4* __restrict__ x4,
                                                    float4* __restrict__ out4) {
    int base = blockIdx.x * 2048 + threadIdx.x;
    float4 v[8];
    float  s[8];
#pragma unroll
    for (int j = 0; j < 8; j++) {
        int i = base + j * 256;
        v[j] = __ldg(&x4[i]);
        s[j] = g_scale[i >> 10];   // 1024 float4 per (b,c)
    }
#pragma unroll
    for (int j = 0; j < 8; j++) {
        int i = base + j * 256;
        float4 o = v[j];
        o.x *= s[j]; o.y *= s[j]; o.z *= s[j]; o.w *= s[j];
        __stcs(&out4[i], o);
    }
}

extern "C" void kernel_launch(void* const* d_in, const int* in_sizes, int n_in,
                              void* d_out, int out_size) {
    const float* x  = (const float*)d_in[0];
    const float* w1 = (const float*)d_in[1];
    const float* b1 = (const float*)d_in[2];
    const float* w2 = (const float*)d_in[3];
    const float* b2 = (const float*)d_in[4];
    float* out = (float*)d_out;

    (void)in_sizes; (void)n_in; (void)out_size;

    const int ns_smem = 4 * 64 * LDP * (int)sizeof(float);
    cudaFuncSetAttribute(ns_kernel, cudaFuncAttributeMaxDynamicSharedMemorySize, ns_smem);

    dim3 gcov(NSPLIT, BATCH);
    cov_kernel<<<gcov, 256>>>(x);
    reduce_kernel<<<BATCH * CC * CC / 256, 256>>>();
    ns_kernel<<<BATCH, 256, ns_smem>>>(w1, b1, w2, b2);
    scale_kernel<<<(BATCH * CC * MM / 4) / 2048, 256>>>((const float4*)x, (float4*)out);
}

// round 6
// speedup vs baseline: 2.9751x; 1.1834x over previous
#include <cuda_runtime.h>
#include <math.h>

#define BATCH  16
#define CC     64
#define MM     4096
#define NSPLIT 16     // 256-col chunk per block -> 256 blocks
#define CHUNK  256
#define LDS    68     // smem row stride (words); 68 % 32 == 4 -> conflict-free frags
#define LDP    68     // ns smem row stride (same property)

// Deterministic scratch (no float atomics)
__device__ float g_part[BATCH * NSPLIT * CC * CC];   // 4 MB partial Grams (L2-resident)
__device__ float g_rspart[BATCH * NSPLIT * CC];
__device__ float g_cov[BATCH * CC * CC];
__device__ float g_scale[BATCH * CC];

__device__ __forceinline__ unsigned cvt_tf32(float f) {
    unsigned r; asm("cvt.rna.tf32.f32 %0, %1;" : "=r"(r) : "f"(f)); return r;
}
__device__ __forceinline__ void mma_tf32(float c[4], unsigned a0, unsigned a1,
                                         unsigned a2, unsigned a3,
                                         unsigned b0, unsigned b1) {
    asm("mma.sync.aligned.m16n8k8.row.col.f32.tf32.tf32.f32 "
        "{%0,%1,%2,%3},{%4,%5,%6,%7},{%8,%9},{%0,%1,%2,%3};"
        : "+f"(c[0]), "+f"(c[1]), "+f"(c[2]), "+f"(c[3])
        : "r"(a0), "r"(a1), "r"(a2), "r"(a3), "r"(b0), "r"(b1));
}

// ---------------------------------------------------------------------------
// Kernel 1: partial X·X^T per (batch, 256-col chunk) via tf32 mma.sync,
// + fp32 partial row sums. grid (NSPLIT, BATCH) = 256 blocks, 256 threads.
// Warp w: rows [16*(w&3), +16), cols [32*(w>>2), +32).
// ---------------------------------------------------------------------------
__global__ __launch_bounds__(256) void cov_kernel(const float* __restrict__ x) {
    __shared__ unsigned buf[64 * LDS];
    const int split = blockIdx.x, b = blockIdx.y;
    const int t = threadIdx.x;
    const int lane = t & 31, w = t >> 5;
    const int m0 = 16 * (w & 3);
    const int n0base = 32 * (w >> 2);
    const int g = lane >> 2, tg = lane & 3;
    const int lrow = t >> 4, lcg = t & 15;
    const float* xb = x + (size_t)b * CC * MM + (size_t)split * CHUNK;

    float c[4][4];
#pragma unroll
    for (int j = 0; j < 4; j++)
#pragma unroll
        for (int q = 0; q < 4; q++) c[j][q] = 0.f;
    float rs[4] = {0.f, 0.f, 0.f, 0.f};

    for (int kb = 0; kb < CHUNK / 64; kb++) {
        __syncthreads();
        // Load 64x64 fp32 sub-tile, accumulate fp32 row sums, store tf32 bits.
#pragma unroll
        for (int j = 0; j < 4; j++) {
            int row = j * 16 + lrow;
            float4 v = *(const float4*)&xb[(size_t)row * MM + kb * 64 + 4 * lcg];
            rs[j] += (v.x + v.y) + (v.z + v.w);
            uint4 u;
            u.x = cvt_tf32(v.x); u.y = cvt_tf32(v.y);
            u.z = cvt_tf32(v.z); u.w = cvt_tf32(v.w);
            *(uint4*)&buf[row * LDS + 4 * lcg] = u;
        }
        __syncthreads();
        // 8 k-steps of m16n8k8; all frag loads conflict-free (LDS%32==4).
#pragma unroll
        for (int k0 = 0; k0 < 64; k0 += 8) {
            unsigned a0 = buf[(m0 + g) * LDS + k0 + tg];
            unsigned a1 = buf[(m0 + g + 8) * LDS + k0 + tg];
            unsigned a2 = buf[(m0 + g) * LDS + k0 + tg + 4];
            unsigned a3 = buf[(m0 + g + 8) * LDS + k0 + tg + 4];
#pragma unroll
            for (int j = 0; j < 4; j++) {
                int n0 = n0base + 8 * j;
                unsigned b0 = buf[(n0 + g) * LDS + k0 + tg];
                unsigned b1 = buf[(n0 + g) * LDS + k0 + tg + 4];
                mma_tf32(c[j], a0, a1, a2, a3, b0, b1);
            }
        }
    }

    // Epilogue: write partial Gram fragments.
    float* P = g_part + (((size_t)(b * NSPLIT + split)) << 12);
#pragma unroll
    for (int j = 0; j < 4; j++) {
        int row = m0 + g, col = n0base + 8 * j + 2 * tg;
        *(float2*)&P[row * 64 + col]       = make_float2(c[j][0], c[j][1]);
        *(float2*)&P[(row + 8) * 64 + col] = make_float2(c[j][2], c[j][3]);
    }

    // Row sums: reduce 16 per-colgroup partials per row via smem scratch.
    __syncthreads();
    float* rsm = (float*)buf;
#pragma unroll
    for (int j = 0; j < 4; j++)
        rsm[(j * 16 + lrow) * 17 + lcg] = rs[j];
    __syncthreads();
    if (t < 64) {
        float s = 0.f;
#pragma unroll
        for (int i = 0; i < 16; i++) s += rsm[t * 17 + i];
        g_rspart[(b * NSPLIT + split) * 64 + t] = s;
    }
}

// ---------------------------------------------------------------------------
// Kernel 2: reduce partial Grams across splits (fully parallel, L2-bound).
// ---------------------------------------------------------------------------
__global__ __launch_bounds__(256) void reduce_kernel() {
    int idx = blockIdx.x * 256 + threadIdx.x;       // 0 .. 16*4096-1
    int b = idx >> 12, e = idx & 4095;
    float s = 0.f;
#pragma unroll
    for (int sp = 0; sp < NSPLIT; sp++)
        s += g_part[(((size_t)(b * NSPLIT + sp)) << 12) + e];
    g_cov[idx] = s;
}

// ---------------------------------------------------------------------------
// 64x64x64 matmul via 3xTF32 mma.sync (fp32-accurate error compensation).
// C = A@B (mode 0) or C = 0.5*(3I - A@B) (mode 1). A, B, C fp32 in smem.
// VALID ONLY FOR SYMMETRIC B (all NS matrices are polynomials of symmetric A):
// the row.col mma's B-operand [n][k] read equals B^T, which equals B.
// 256 threads = 8 warps; warp w: rows 16*(w&3)+, cols 32*(w>>2)+.
// Precondition: operands visible. Postcondition: C visible.
// ---------------------------------------------------------------------------
__device__ __forceinline__ void mm64t(float* __restrict__ C, const float* __restrict__ A,
                                      const float* __restrict__ B, int w, int lane, int mode) {
    const int m0 = 16 * (w & 3);
    const int n0b = 32 * (w >> 2);
    const int g = lane >> 2, tg = lane & 3;

    float c[4][4];
#pragma unroll
    for (int j = 0; j < 4; j++)
#pragma unroll
        for (int q = 0; q < 4; q++) c[j][q] = 0.f;

#pragma unroll
    for (int k0 = 0; k0 < 64; k0 += 8) {
        float af0 = A[(m0 + g) * LDP + k0 + tg];
        float af1 = A[(m0 + g + 8) * LDP + k0 + tg];
        float af2 = A[(m0 + g) * LDP + k0 + tg + 4];
        float af3 = A[(m0 + g + 8) * LDP + k0 + tg + 4];
        unsigned ah0 = cvt_tf32(af0), ah1 = cvt_tf32(af1);
        unsigned ah2 = cvt_tf32(af2), ah3 = cvt_tf32(af3);
        unsigned al0 = cvt_tf32(af0 - __uint_as_float(ah0));
        unsigned al1 = cvt_tf32(af1 - __uint_as_float(ah1));
        unsigned al2 = cvt_tf32(af2 - __uint_as_float(ah2));
        unsigned al3 = cvt_tf32(af3 - __uint_as_float(ah3));
#pragma unroll
        for (int j = 0; j < 4; j++) {
            int n0 = n0b + 8 * j;
            float bf0 = B[(n0 + g) * LDP + k0 + tg];
            float bf1 = B[(n0 + g) * LDP + k0 + tg + 4];
            unsigned bh0 = cvt_tf32(bf0), bh1 = cvt_tf32(bf1);
            unsigned bl0 = cvt_tf32(bf0 - __uint_as_float(bh0));
            unsigned bl1 = cvt_tf32(bf1 - __uint_as_float(bh1));
            mma_tf32(c[j], al0, al1, al2, al3, bh0, bh1);  // lo*hi
            mma_tf32(c[j], ah0, ah1, ah2, ah3, bl0, bl1);  // hi*lo
            mma_tf32(c[j], ah0, ah1, ah2, ah3, bh0, bh1);  // hi*hi
        }
    }
    __syncthreads();   // all operand reads done before C overwrites anything
#pragma unroll
    for (int j = 0; j < 4; j++) {
        int col = n0b + 8 * j + 2 * tg;
        int r0 = m0 + g, r1 = m0 + g + 8;
        float v0 = c[j][0], v1 = c[j][1], v2 = c[j][2], v3 = c[j][3];
        if (mode) {
            v0 = 0.5f * (((r0 == col)     ? 3.f : 0.f) - v0);
            v1 = 0.5f * (((r0 == col + 1) ? 3.f : 0.f) - v1);
            v2 = 0.5f * (((r1 == col)     ? 3.f : 0.f) - v2);
            v3 = 0.5f * (((r1 == col + 1) ? 3.f : 0.f) - v3);
        }
        *(float2*)&C[r0 * LDP + col] = make_float2(v0, v1);
        *(float2*)&C[r1 * LDP + col] = make_float2(v2, v3);
    }
    __syncthreads();   // C visible
}

// ---------------------------------------------------------------------------
// Kernel 3: covariance assembly + Newton-Schulz (tensor) + center-tap convs.
// 16 blocks x 256 threads. Dynamic smem: 4 matrices [64][LDP].
// ---------------------------------------------------------------------------
__global__ __launch_bounds__(256) void ns_kernel(const float* __restrict__ w1, const float* __restrict__ b1,
                                                 const float* __restrict__ w2, const float* __restrict__ b2) {
    extern __shared__ float sm[];
    float* S0 = sm;
    float* S1 = sm + 64 * LDP;
    float* S2 = sm + 2 * 64 * LDP;
    float* S3 = sm + 3 * 64 * LDP;
    __shared__ float svec[64];
    __shared__ float vvec[64];
    __shared__ float red[8];
    __shared__ float snorm;

    const int b = blockIdx.x, t = threadIdx.x;
    const int lane = t & 31, w = t >> 5;
    const float invM = 1.0f / (float)MM;
    const float invM2 = invM * invM;

    // row sums
    if (t < 64) {
        float s = 0.f;
#pragma unroll
        for (int sp = 0; sp < NSPLIT; sp++) s += g_rspart[(b * NSPLIT + sp) * 64 + t];
        svec[t] = s;
    }
    __syncthreads();

    // cov = Sxx/M - s s^T / M^2 ; normA = sum(cov)
    float lsum = 0.f;
#pragma unroll
    for (int e = 0; e < 16; e++) {
        int idx = e * 256 + t;
        int i = idx >> 6, j = idx & 63;
        float cv = invM * g_cov[b * 4096 + idx] - invM2 * svec[i] * svec[j];
        S0[i * LDP + j] = cv;
        lsum += cv;
    }
#pragma unroll
    for (int o = 16; o; o >>= 1) lsum += __shfl_xor_sync(0xffffffffu, lsum, o);
    if ((t & 31) == 0) red[t >> 5] = lsum;
    __syncthreads();
    if (t == 0) { float s = 0.f; for (int q = 0; q < 8; q++) s += red[q]; snorm = s; }
    __syncthreads();

    const float invN = 1.f / snorm;
#pragma unroll
    for (int e = 0; e < 16; e++) {
        int idx = e * 256 + t;
        int i = idx >> 6, j = idx & 63;
        float a = S0[i * LDP + j] * invN;
        S0[i * LDP + j] = a;
        float zy = 0.5f * (((i == j) ? 3.f : 0.f) - a);
        S3[i * LDP + j] = zy;   // ZY
        S2[i * LDP + j] = zy;   // Z = ZY
    }
    __syncthreads();

    mm64t(S1, S0, S3, w, lane, 0);   // Y = A @ ZY

    float* pY = S1; float* pZ = S2; float* pT = S0; float* pU = S3;
    for (int it = 0; it < 3; it++) {
        mm64t(pT, pZ, pY, w, lane, 1);   // T = 0.5(3I - Z@Y) = ZYnew
        mm64t(pU, pY, pT, w, lane, 0);   // U = Ynew = Y @ ZYnew
        mm64t(pY, pT, pZ, w, lane, 0);   // (old Y slot) = Znew = ZYnew @ Z
        float* oY = pY; float* oZ = pZ; float* oT = pT; float* oU = pU;
        pY = oU; pZ = oY; pT = oT; pU = oZ;
    }

    // Stage conv center taps into the two dead smem matrices (parallel loads).
    float* W1 = pT;
    float* W2 = pU;
#pragma unroll
    for (int e = 0; e < 16; e++) {
        int n = e * 256 + t;                 // n = outc*64 + inc
        W1[n] = w1[n * 9 + 4];
        W2[n] = w2[n * 9 + 4];
    }

    // y_vec = (0.5/64)*sqrt(normA) * (3u - (u^T Z) Y), u = colsum(Y)
    __syncthreads();
    if (t < 64) {
        float u = 0.f;
        for (int i = 0; i < 64; i++) u += pY[i * LDP + t];
        svec[t] = u;
    }
    __syncthreads();
    if (t < 64) {
        float vv = 0.f;
        for (int i = 0; i < 64; i++) vv += svec[i] * pZ[i * LDP + t];
        vvec[t] = vv;
    }
    __syncthreads();
    if (t < 64) {
        float wv = 0.f;
        for (int k = 0; k < 64; k++) wv += vvec[k] * pY[k * LDP + t];
        float c = (0.5f / 64.f) * sqrtf(snorm);
        svec[t] = c * (3.f * svec[t] - wv);   // y_vec
    }
    __syncthreads();
    // conv1 center tap + bias + relu
    if (t < 64) {
        float a = b1[t];
        for (int i = 0; i < 64; i++) a += W1[t * 64 + i] * svec[i];
        vvec[t] = fmaxf(a, 0.f);
    }
    __syncthreads();
    // conv2 center tap + bias + sigmoid
    if (t < 64) {
        float a = b2[t];
        for (int i = 0; i < 64; i++) a += W2[t * 64 + i] * vvec[i];
        g_scale[b * 64 + t] = 1.f / (1.f + expf(-a));
    }
}

// ---------------------------------------------------------------------------
// Kernel 4: out = scale[b,c] * x. One float4 per thread, max warp parallelism;
// streaming stores keep x L2-resident for the reads.
// ---------------------------------------------------------------------------
__global__ __launch_bounds__(256) void scale_kernel(const float4* __restrict__ x4,
                                                    float4* __restrict__ out4) {
    int i = blockIdx.x * 256 + threadIdx.x;
    float s = g_scale[i >> 10];   // 1024 float4 per (b,c)
    float4 v = __ldg(&x4[i]);
    v.x *= s; v.y *= s; v.z *= s; v.w *= s;
    __stcs(&out4[i], v);
}

extern "C" void kernel_launch(void* const* d_in, const int* in_sizes, int n_in,
                              void* d_out, int out_size) {
    const float* x  = (const float*)d_in[0];
    const float* w1 = (const float*)d_in[1];
    const float* b1 = (const float*)d_in[2];
    const float* w2 = (const float*)d_in[3];
    const float* b2 = (const float*)d_in[4];
    float* out = (float*)d_out;

    (void)in_sizes; (void)n_in; (void)out_size;

    const int ns_smem = 4 * 64 * LDP * (int)sizeof(float);
    cudaFuncSetAttribute(ns_kernel, cudaFuncAttributeMaxDynamicSharedMemorySize, ns_smem);

    dim3 gcov(NSPLIT, BATCH);
    cov_kernel<<<gcov, 256>>>(x);
    reduce_kernel<<<BATCH * CC * CC / 256, 256>>>();
    ns_kernel<<<BATCH, 256, ns_smem>>>(w1, b1, w2, b2);
    scale_kernel<<<(BATCH * CC * MM / 4) / 256, 256>>>((const float4*)x, (float4*)out);
}

// round 7
// speedup vs baseline: 3.8439x; 1.2920x over previous
#include <cuda_runtime.h>
#include <math.h>

#define BATCH  16
#define CC     64
#define MM     4096
#define NSPLIT 32     // 128-col chunk per block -> 512 blocks
#define CHUNK  128
#define LDS    68     // smem row stride (words); 68 % 32 == 4 -> conflict-free frags
#define LDP    68     // ns smem row stride (same property)

// Deterministic scratch (no float atomics)
__device__ float g_part[BATCH * NSPLIT * CC * CC];   // 8 MB partial Grams (L2-resident)
__device__ float g_rspart[BATCH * NSPLIT * CC];
__device__ float g_cov[BATCH * CC * CC];
__device__ float g_scale[BATCH * CC];

__device__ __forceinline__ unsigned cvt_tf32(float f) {
    unsigned r; asm("cvt.rna.tf32.f32 %0, %1;" : "=r"(r) : "f"(f)); return r;
}
__device__ __forceinline__ void mma_tf32(float c[4], unsigned a0, unsigned a1,
                                         unsigned a2, unsigned a3,
                                         unsigned b0, unsigned b1) {
    asm("mma.sync.aligned.m16n8k8.row.col.f32.tf32.tf32.f32 "
        "{%0,%1,%2,%3},{%4,%5,%6,%7},{%8,%9},{%0,%1,%2,%3};"
        : "+f"(c[0]), "+f"(c[1]), "+f"(c[2]), "+f"(c[3])
        : "r"(a0), "r"(a1), "r"(a2), "r"(a3), "r"(b0), "r"(b1));
}

// ---------------------------------------------------------------------------
// Kernel 1: partial X·X^T per (batch, 128-col chunk) via tf32 mma.sync,
// + fp32 partial row sums. grid (NSPLIT, BATCH) = 512 blocks, 256 threads.
// Warp w: rows [16*(w&3), +16), cols [32*(w>>2), +32).
// ---------------------------------------------------------------------------
__global__ __launch_bounds__(256) void cov_kernel(const float* __restrict__ x) {
    __shared__ unsigned buf[64 * LDS];
    const int split = blockIdx.x, b = blockIdx.y;
    const int t = threadIdx.x;
    const int lane = t & 31, w = t >> 5;
    const int m0 = 16 * (w & 3);
    const int n0base = 32 * (w >> 2);
    const int g = lane >> 2, tg = lane & 3;
    const int lrow = t >> 4, lcg = t & 15;
    const float* xb = x + (size_t)b * CC * MM + (size_t)split * CHUNK;

    float c[4][4];
#pragma unroll
    for (int j = 0; j < 4; j++)
#pragma unroll
        for (int q = 0; q < 4; q++) c[j][q] = 0.f;
    float rs[4] = {0.f, 0.f, 0.f, 0.f};

    for (int kb = 0; kb < CHUNK / 64; kb++) {
        __syncthreads();
        // Load 64x64 fp32 sub-tile, accumulate fp32 row sums, store tf32 bits.
#pragma unroll
        for (int j = 0; j < 4; j++) {
            int row = j * 16 + lrow;
            float4 v = *(const float4*)&xb[(size_t)row * MM + kb * 64 + 4 * lcg];
            rs[j] += (v.x + v.y) + (v.z + v.w);
            uint4 u;
            u.x = cvt_tf32(v.x); u.y = cvt_tf32(v.y);
            u.z = cvt_tf32(v.z); u.w = cvt_tf32(v.w);
            *(uint4*)&buf[row * LDS + 4 * lcg] = u;
        }
        __syncthreads();
        // 8 k-steps of m16n8k8; all frag loads conflict-free (LDS%32==4).
#pragma unroll
        for (int k0 = 0; k0 < 64; k0 += 8) {
            unsigned a0 = buf[(m0 + g) * LDS + k0 + tg];
            unsigned a1 = buf[(m0 + g + 8) * LDS + k0 + tg];
            unsigned a2 = buf[(m0 + g) * LDS + k0 + tg + 4];
            unsigned a3 = buf[(m0 + g + 8) * LDS + k0 + tg + 4];
#pragma unroll
            for (int j = 0; j < 4; j++) {
                int n0 = n0base + 8 * j;
                unsigned b0 = buf[(n0 + g) * LDS + k0 + tg];
                unsigned b1 = buf[(n0 + g) * LDS + k0 + tg + 4];
                mma_tf32(c[j], a0, a1, a2, a3, b0, b1);
            }
        }
    }

    // Epilogue: write partial Gram fragments.
    float* P = g_part + (((size_t)(b * NSPLIT + split)) << 12);
#pragma unroll
    for (int j = 0; j < 4; j++) {
        int row = m0 + g, col = n0base + 8 * j + 2 * tg;
        *(float2*)&P[row * 64 + col]       = make_float2(c[j][0], c[j][1]);
        *(float2*)&P[(row + 8) * 64 + col] = make_float2(c[j][2], c[j][3]);
    }

    // Row sums: reduce 16 per-colgroup partials per row via smem scratch.
    __syncthreads();
    float* rsm = (float*)buf;
#pragma unroll
    for (int j = 0; j < 4; j++)
        rsm[(j * 16 + lrow) * 17 + lcg] = rs[j];
    __syncthreads();
    if (t < 64) {
        float s = 0.f;
#pragma unroll
        for (int i = 0; i < 16; i++) s += rsm[t * 17 + i];
        g_rspart[(b * NSPLIT + split) * 64 + t] = s;
    }
}

// ---------------------------------------------------------------------------
// Kernel 2: reduce partial Grams across splits (fully parallel, L2-bound).
// ---------------------------------------------------------------------------
__global__ __launch_bounds__(256) void reduce_kernel() {
    int idx = blockIdx.x * 256 + threadIdx.x;       // 0 .. 16*4096-1
    int b = idx >> 12, e = idx & 4095;
    float s = 0.f;
#pragma unroll
    for (int sp = 0; sp < NSPLIT; sp++)
        s += g_part[(((size_t)(b * NSPLIT + sp)) << 12) + e];
    g_cov[idx] = s;
}

// ---------------------------------------------------------------------------
// 64x64x64 matmul via single tf32 mma.sync. NS is self-correcting and the
// SE tail attenuates ~100x, so tf32 error (~1e-4) lands ~1e-6 at the output.
// C = A@B (mode 0) or C = 0.5*(3I - A@B) (mode 1). A, B, C fp32 in smem.
// VALID ONLY FOR SYMMETRIC B (all NS matrices are polynomials of symmetric A).
// 256 threads = 8 warps; warp w: rows 16*(w&3)+, cols 32*(w>>2)+.
// ---------------------------------------------------------------------------
__device__ __forceinline__ void mm64t(float* __restrict__ C, const float* __restrict__ A,
                                      const float* __restrict__ B, int w, int lane, int mode) {
    const int m0 = 16 * (w & 3);
    const int n0b = 32 * (w >> 2);
    const int g = lane >> 2, tg = lane & 3;

    float c[4][4];
#pragma unroll
    for (int j = 0; j < 4; j++)
#pragma unroll
        for (int q = 0; q < 4; q++) c[j][q] = 0.f;

#pragma unroll
    for (int k0 = 0; k0 < 64; k0 += 8) {
        unsigned a0 = cvt_tf32(A[(m0 + g) * LDP + k0 + tg]);
        unsigned a1 = cvt_tf32(A[(m0 + g + 8) * LDP + k0 + tg]);
        unsigned a2 = cvt_tf32(A[(m0 + g) * LDP + k0 + tg + 4]);
        unsigned a3 = cvt_tf32(A[(m0 + g + 8) * LDP + k0 + tg + 4]);
#pragma unroll
        for (int j = 0; j < 4; j++) {
            int n0 = n0b + 8 * j;
            unsigned b0 = cvt_tf32(B[(n0 + g) * LDP + k0 + tg]);
            unsigned b1 = cvt_tf32(B[(n0 + g) * LDP + k0 + tg + 4]);
            mma_tf32(c[j], a0, a1, a2, a3, b0, b1);
        }
    }
    __syncthreads();   // all operand reads done before C overwrites anything
#pragma unroll
    for (int j = 0; j < 4; j++) {
        int col = n0b + 8 * j + 2 * tg;
        int r0 = m0 + g, r1 = m0 + g + 8;
        float v0 = c[j][0], v1 = c[j][1], v2 = c[j][2], v3 = c[j][3];
        if (mode) {
            v0 = 0.5f * (((r0 == col)     ? 3.f : 0.f) - v0);
            v1 = 0.5f * (((r0 == col + 1) ? 3.f : 0.f) - v1);
            v2 = 0.5f * (((r1 == col)     ? 3.f : 0.f) - v2);
            v3 = 0.5f * (((r1 == col + 1) ? 3.f : 0.f) - v3);
        }
        *(float2*)&C[r0 * LDP + col] = make_float2(v0, v1);
        *(float2*)&C[r1 * LDP + col] = make_float2(v2, v3);
    }
    __syncthreads();   // C visible
}

// ---------------------------------------------------------------------------
// Kernel 3: covariance assembly + Newton-Schulz (tensor) + center-tap convs.
// 16 blocks x 256 threads. Dynamic smem: 4 matrices [64][LDP].
// ---------------------------------------------------------------------------
__global__ __launch_bounds__(256) void ns_kernel(const float* __restrict__ w1, const float* __restrict__ b1,
                                                 const float* __restrict__ w2, const float* __restrict__ b2) {
    extern __shared__ float sm[];
    float* S0 = sm;
    float* S1 = sm + 64 * LDP;
    float* S2 = sm + 2 * 64 * LDP;
    float* S3 = sm + 3 * 64 * LDP;
    __shared__ float svec[64];
    __shared__ float vvec[64];
    __shared__ float red[8];
    __shared__ float snorm;

    const int b = blockIdx.x, t = threadIdx.x;
    const int lane = t & 31, w = t >> 5;
    const float invM = 1.0f / (float)MM;
    const float invM2 = invM * invM;

    // row sums
    if (t < 64) {
        float s = 0.f;
#pragma unroll
        for (int sp = 0; sp < NSPLIT; sp++) s += g_rspart[(b * NSPLIT + sp) * 64 + t];
        svec[t] = s;
    }
    __syncthreads();

    // cov = Sxx/M - s s^T / M^2 ; normA = sum(cov)
    float lsum = 0.f;
#pragma unroll
    for (int e = 0; e < 16; e++) {
        int idx = e * 256 + t;
        int i = idx >> 6, j = idx & 63;
        float cv = invM * g_cov[b * 4096 + idx] - invM2 * svec[i] * svec[j];
        S0[i * LDP + j] = cv;
        lsum += cv;
    }
#pragma unroll
    for (int o = 16; o; o >>= 1) lsum += __shfl_xor_sync(0xffffffffu, lsum, o);
    if ((t & 31) == 0) red[t >> 5] = lsum;
    __syncthreads();
    if (t == 0) { float s = 0.f; for (int q = 0; q < 8; q++) s += red[q]; snorm = s; }
    __syncthreads();

    const float invN = 1.f / snorm;
#pragma unroll
    for (int e = 0; e < 16; e++) {
        int idx = e * 256 + t;
        int i = idx >> 6, j = idx & 63;
        float a = S0[i * LDP + j] * invN;
        S0[i * LDP + j] = a;
        float zy = 0.5f * (((i == j) ? 3.f : 0.f) - a);
        S3[i * LDP + j] = zy;   // ZY
        S2[i * LDP + j] = zy;   // Z = ZY
    }
    __syncthreads();

    mm64t(S1, S0, S3, w, lane, 0);   // Y = A @ ZY

    float* pY = S1; float* pZ = S2; float* pT = S0; float* pU = S3;
    for (int it = 0; it < 3; it++) {
        mm64t(pT, pZ, pY, w, lane, 1);   // T = 0.5(3I - Z@Y) = ZYnew
        mm64t(pU, pY, pT, w, lane, 0);   // U = Ynew = Y @ ZYnew
        mm64t(pY, pT, pZ, w, lane, 0);   // (old Y slot) = Znew = ZYnew @ Z
        float* oY = pY; float* oZ = pZ; float* oT = pT; float* oU = pU;
        pY = oU; pZ = oY; pT = oT; pU = oZ;
    }

    // Stage conv center taps into the two dead smem matrices (parallel loads).
    float* W1 = pT;
    float* W2 = pU;
#pragma unroll
    for (int e = 0; e < 16; e++) {
        int n = e * 256 + t;                 // n = outc*64 + inc
        W1[n] = w1[n * 9 + 4];
        W2[n] = w2[n * 9 + 4];
    }

    // y_vec = (0.5/64)*sqrt(normA) * (3u - (u^T Z) Y), u = colsum(Y)
    __syncthreads();
    if (t < 64) {
        float u = 0.f;
        for (int i = 0; i < 64; i++) u += pY[i * LDP + t];
        svec[t] = u;
    }
    __syncthreads();
    if (t < 64) {
        float vv = 0.f;
        for (int i = 0; i < 64; i++) vv += svec[i] * pZ[i * LDP + t];
        vvec[t] = vv;
    }
    __syncthreads();
    if (t < 64) {
        float wv = 0.f;
        for (int k = 0; k < 64; k++) wv += vvec[k] * pY[k * LDP + t];
        float c = (0.5f / 64.f) * sqrtf(snorm);
        svec[t] = c * (3.f * svec[t] - wv);   // y_vec
    }
    __syncthreads();
    // conv1 center tap + bias + relu
    if (t < 64) {
        float a = b1[t];
        for (int i = 0; i < 64; i++) a += W1[t * 64 + i] * svec[i];
        vvec[t] = fmaxf(a, 0.f);
    }
    __syncthreads();
    // conv2 center tap + bias + sigmoid
    if (t < 64) {
        float a = b2[t];
        for (int i = 0; i < 64; i++) a += W2[t * 64 + i] * vvec[i];
        g_scale[b * 64 + t] = 1.f / (1.f + expf(-a));
    }
}

// ---------------------------------------------------------------------------
// Kernel 4: out = scale[b,c] * x via cp.async.bulk (TMA path) — bypasses the
// STG issue-cost floor (~12 cyc/STG.128/SMSP) that capped SIMT stores at ~2TB/s.
// 512 blocks, each: bulk-load 32KB -> smem, multiply in place, bulk-store.
// ---------------------------------------------------------------------------
__global__ __launch_bounds__(256) void scale_kernel(const float* __restrict__ x,
                                                    float* __restrict__ out) {
    __shared__ __align__(16) float sbuf[8192];   // 32 KB = 2 channels
    __shared__ __align__(8) unsigned long long mbar;
    const int t = threadIdx.x;
    const size_t base = (size_t)blockIdx.x * 8192;

    unsigned sb = (unsigned)__cvta_generic_to_shared(sbuf);
    unsigned mb = (unsigned)__cvta_generic_to_shared(&mbar);

    if (t == 0) {
        asm volatile("mbarrier.init.shared.b64 [%0], 1;" :: "r"(mb) : "memory");
        asm volatile("mbarrier.arrive.expect_tx.shared.b64 _, [%0], %1;"
                     :: "r"(mb), "r"(32768u) : "memory");
        asm volatile("cp.async.bulk.shared::cta.global.mbarrier::complete_tx::bytes "
                     "[%0], [%1], %2, [%3];"
                     :: "r"(sb), "l"(x + base), "r"(32768u), "r"(mb) : "memory");
    }
    __syncthreads();
    // Wait for bulk load completion (phase 0).
    asm volatile(
        "{\n\t.reg .pred p;\n"
        "WL%=:\n\t"
        "mbarrier.try_wait.parity.shared.b64 p, [%0], 0, 0x989680;\n\t"
        "@!p bra WL%=;\n\t}"
        :: "r"(mb) : "memory");

    // Multiply in place: 8 float4 per thread; channel = global float4 idx >> 10.
    float4* s4 = (float4*)sbuf;
    const int gbase = blockIdx.x * 2048;
#pragma unroll
    for (int j = 0; j < 8; j++) {
        int li = j * 256 + t;
        float s = g_scale[(gbase + li) >> 10];
        float4 v = s4[li];
        v.x *= s; v.y *= s; v.z *= s; v.w *= s;
        s4[li] = v;
    }
    __syncthreads();
    asm volatile("fence.proxy.async.shared::cta;" ::: "memory");
    if (t == 0) {
        asm volatile("cp.async.bulk.global.shared::cta.bulk_group [%0], [%1], %2;"
                     :: "l"(out + base), "r"(sb), "r"(32768u) : "memory");
        asm volatile("cp.async.bulk.commit_group;" ::: "memory");
        asm volatile("cp.async.bulk.wait_group.read 0;" ::: "memory");
    }
}

extern "C" void kernel_launch(void* const* d_in, const int* in_sizes, int n_in,
                              void* d_out, int out_size) {
    const float* x  = (const float*)d_in[0];
    const float* w1 = (const float*)d_in[1];
    const float* b1 = (const float*)d_in[2];
    const float* w2 = (const float*)d_in[3];
    const float* b2 = (const float*)d_in[4];
    float* out = (float*)d_out;

    (void)in_sizes; (void)n_in; (void)out_size;

    const int ns_smem = 4 * 64 * LDP * (int)sizeof(float);
    cudaFuncSetAttribute(ns_kernel, cudaFuncAttributeMaxDynamicSharedMemorySize, ns_smem);

    dim3 gcov(NSPLIT, BATCH);
    cov_kernel<<<gcov, 256>>>(x);
    reduce_kernel<<<BATCH * CC * CC / 256, 256>>>();
    ns_kernel<<<BATCH, 256, ns_smem>>>(w1, b1, w2, b2);
    scale_kernel<<<(BATCH * CC * MM) / 8192, 256>>>(x, out);
}